// round 7
// baseline (speedup 1.0000x reference)
#include <cuda_runtime.h>
#include <math.h>

namespace {

constexpr int B = 128;
constexpr int N = 2048;
constexpr int E = 32768;
constexpr float INV_SQRT_DH = 0.7071067811865476f;

// Interleaved accumulators: per node 8 floats = [agg0..3 | s0 s1 | pad pad].
// One buffer per layer so no resets are needed between passes.
__device__ float g_acc0[B * N * 8];   // 8 MB
__device__ float g_acc1[B * N * 8];   // 8 MB

// Weights in constant memory (filled by capturable D2D copies each launch)
__constant__ float cWq[2 * 16];
__constant__ float cWk[2 * 32];
__constant__ float cWv[2 * 32];
__constant__ float cWo[2 * 16];
__constant__ float cbo[2 * 4];
__constant__ float ctw[4];
__constant__ float ctb[4];
__constant__ float cWlin[24];
__constant__ float cblin[2];

// Node update for layer L: h_next = relu(h + (agg/s) @ Wo[L] + bo[L])
__device__ __forceinline__ float4 node_update(int L, float4 h,
                                              float4 agg, float4 sv) {
    float s0 = (sv.x == 0.0f) ? 1.0f : sv.x;
    float s1 = (sv.y == 0.0f) ? 1.0f : sv.y;
    float r0 = __frcp_rn(s0);
    float r1 = __frcp_rn(s1);
    float a0 = agg.x * r0, a1 = agg.y * r0;
    float a2 = agg.z * r1, a3 = agg.w * r1;
    const float* Wo = cWo + L * 16;
    const float* bo = cbo + L * 4;
    float hn[4];
    float hin[4] = {h.x, h.y, h.z, h.w};
#pragma unroll
    for (int j = 0; j < 4; j++) {
        float v = hin[j] + bo[j];
        v = fmaf(a0, Wo[0 * 4 + j], v);
        v = fmaf(a1, Wo[1 * 4 + j], v);
        v = fmaf(a2, Wo[2 * 4 + j], v);
        v = fmaf(a3, Wo[3 * 4 + j], v);
        hn[j] = fmaxf(v, 0.0f);
    }
    return make_float4(hn[0], hn[1], hn[2], hn[3]);
}

// ---------------------------------------------------------------------------
// Init: zero both accumulator buffers.
// ---------------------------------------------------------------------------
__global__ void __launch_bounds__(256) init_kernel() {
    int idx = blockIdx.x * blockDim.x + threadIdx.x;   // 0 .. B*N-1
    float4 z = make_float4(0.f, 0.f, 0.f, 0.f);
    reinterpret_cast<float4*>(g_acc0)[idx * 2 + 0] = z;
    reinterpret_cast<float4*>(g_acc0)[idx * 2 + 1] = z;
    reinterpret_cast<float4*>(g_acc1)[idx * 2 + 0] = z;
    reinterpret_cast<float4*>(g_acc1)[idx * 2 + 1] = z;
}

// ---------------------------------------------------------------------------
// Edge pass. L=0: stage h0 = x into smem, RED into acc0.
//            L=1: stage h1 = node_update(0, x, acc0) into smem, RED into acc1.
// ---------------------------------------------------------------------------
constexpr int BPB = 8;                         // blocks per batch
constexpr int EDGE_THREADS = 256;
constexpr int EDGES_PER_BLOCK = E / BPB;       // 4096
constexpr int EDGE_ITERS = EDGES_PER_BLOCK / EDGE_THREADS;  // 16
constexpr int EDGE_SMEM = N * 16;              // 32 KB (h tile)

template <int L>
__global__ void __launch_bounds__(EDGE_THREADS, 6) edge_pass(
        const float* __restrict__ x,
        const int*   __restrict__ edge_index,
        const float* __restrict__ edge_time,
        const float* __restrict__ timestamp) {
    extern __shared__ float4 sh[];   // h tile, N float4

    int b     = blockIdx.x >> 3;
    int chunk = blockIdx.x & 7;

    // Stage this batch's h tile (coalesced). For L=1, fold in the layer-0
    // node update so no separate node kernel or h round-trip is needed.
    const float4* x4 = reinterpret_cast<const float4*>(x) + b * N;
    if (L == 0) {
#pragma unroll
        for (int i = threadIdx.x; i < N; i += EDGE_THREADS) sh[i] = x4[i];
    } else {
        const float4* a0 = reinterpret_cast<const float4*>(g_acc0) + (size_t)b * N * 2;
#pragma unroll
        for (int i = threadIdx.x; i < N; i += EDGE_THREADS) {
            float4 h0  = x4[i];
            float4 agg = __ldg(a0 + i * 2 + 0);
            float4 sv  = __ldg(a0 + i * 2 + 1);
            sh[i] = node_update(0, h0, agg, sv);
        }
    }
    __syncthreads();

    const float* Wk = cWk + L * 32;
    const float* Wv = cWv + L * 32;
    const float* Wq = cWq + L * 16;

    int base = chunk * EDGES_PER_BLOCK;
    const int*   e_src = edge_index + (size_t)b * 2 * E + base;
    const int*   e_dst = e_src + E;
    const float* e_t   = edge_time + (size_t)b * E + base;
    float ts = __ldg(timestamp + b);

    float* acc_base = (L == 0 ? g_acc0 : g_acc1) + (size_t)b * N * 8;

    // Software pipeline: prefetch next iteration's edge tuple.
    int e = threadIdx.x;
    int src = __ldg(e_src + e);
    int dst = __ldg(e_dst + e);
    float t = __ldg(e_t + e);

#pragma unroll
    for (int it = 0; it < EDGE_ITERS; it++) {
        int nsrc = 0, ndst = 0;
        float nt = 0.0f;
        if (it + 1 < EDGE_ITERS) {
            int ne = e + EDGE_THREADS;
            nsrc = __ldg(e_src + ne);
            ndst = __ldg(e_dst + ne);
            nt   = __ldg(e_t + ne);
        }

        float dt = ts - t;
        float4 hs = sh[src];
        float msg[8];
        msg[0] = hs.x; msg[1] = hs.y; msg[2] = hs.z; msg[3] = hs.w;
#pragma unroll
        for (int j = 0; j < 4; j++) msg[4 + j] = __cosf(fmaf(dt, ctw[j], ctb[j]));

        float k[4];
#pragma unroll
        for (int j = 0; j < 4; j++) {
            float acc = msg[0] * Wk[0 * 4 + j];
#pragma unroll
            for (int i = 1; i < 8; i++) acc = fmaf(msg[i], Wk[i * 4 + j], acc);
            k[j] = acc;
        }

        float4 hd = sh[dst];
        float q[4];
#pragma unroll
        for (int j = 0; j < 4; j++) {
            float acc = hd.x * Wq[0 * 4 + j];
            acc = fmaf(hd.y, Wq[1 * 4 + j], acc);
            acc = fmaf(hd.z, Wq[2 * 4 + j], acc);
            acc = fmaf(hd.w, Wq[3 * 4 + j], acc);
            q[j] = acc;
        }

        float l0 = (q[0] * k[0] + q[1] * k[1]) * INV_SQRT_DH;
        float l1 = (q[2] * k[2] + q[3] * k[3]) * INV_SQRT_DH;
        float p0 = __expf(fminf(l0, 80.0f));
        float p1 = __expf(fminf(l1, 80.0f));

        float v[4];
#pragma unroll
        for (int j = 0; j < 4; j++) {
            float acc = msg[0] * Wv[0 * 4 + j];
#pragma unroll
            for (int i = 1; i < 8; i++) acc = fmaf(msg[i], Wv[i * 4 + j], acc);
            v[j] = acc;
        }

        float* nodeacc = acc_base + dst * 8;
        atomicAdd(reinterpret_cast<float4*>(nodeacc),
                  make_float4(p0 * v[0], p0 * v[1], p1 * v[2], p1 * v[3]));
        atomicAdd(reinterpret_cast<float2*>(nodeacc + 4),
                  make_float2(p0, p1));

        src = nsrc; dst = ndst; t = nt;
        e += EDGE_THREADS;
    }
}

// ---------------------------------------------------------------------------
// Final: recompute h1 then h2 at the 2 needed nodes per batch (256 nodes),
// then the linear head. One block, 256 threads.
// ---------------------------------------------------------------------------
__global__ void __launch_bounds__(256) final_kernel(
        const float* __restrict__ x,
        const int*   __restrict__ src_index,
        const int*   __restrict__ dst_index,
        const float* __restrict__ timestamp,
        float* __restrict__ out) {
    __shared__ float4 sh2[256];

    int tid = threadIdx.x;           // 0..255
    int b = tid >> 1;
    int node = (tid & 1) ? dst_index[b] : src_index[b];
    size_t idx = (size_t)b * N + node;

    float4 h0  = reinterpret_cast<const float4*>(x)[idx];
    float4 ag0 = reinterpret_cast<const float4*>(g_acc0)[idx * 2 + 0];
    float4 sv0 = reinterpret_cast<const float4*>(g_acc0)[idx * 2 + 1];
    float4 h1  = node_update(0, h0, ag0, sv0);
    float4 ag1 = reinterpret_cast<const float4*>(g_acc1)[idx * 2 + 0];
    float4 sv1 = reinterpret_cast<const float4*>(g_acc1)[idx * 2 + 1];
    float4 h2  = node_update(1, h1, ag1, sv1);

    sh2[tid] = h2;
    __syncthreads();

    if (tid < B) {
        float4 hs = sh2[tid * 2 + 0];
        float4 hd = sh2[tid * 2 + 1];
        float ts = timestamp[tid];

        float f[12];
        f[0] = hs.x; f[1] = hs.y; f[2] = hs.z; f[3] = hs.w;
        f[4] = hd.x; f[5] = hd.y; f[6] = hd.z; f[7] = hd.w;
#pragma unroll
        for (int j = 0; j < 4; j++) f[8 + j] = cosf(fmaf(ts, ctw[j], ctb[j]));

#pragma unroll
        for (int k = 0; k < 2; k++) {
            float acc = cblin[k];
#pragma unroll
            for (int i = 0; i < 12; i++) acc = fmaf(f[i], cWlin[i * 2 + k], acc);
            out[tid * 2 + k] = acc;
        }
    }
}

} // anonymous namespace

extern "C" void kernel_launch(void* const* d_in, const int* in_sizes, int n_in,
                              void* d_out, int out_size) {
    const float* x          = (const float*)d_in[0];
    const int*   edge_index = (const int*)  d_in[1];
    const float* edge_time  = (const float*)d_in[2];
    const float* timestamp  = (const float*)d_in[3];
    const int*   src_index  = (const int*)  d_in[4];
    const int*   dst_index  = (const int*)  d_in[5];
    float* out = (float*)d_out;

    // Stage all weights into constant memory (device-to-device, capturable).
    cudaMemcpyToSymbolAsync(cWq,   d_in[8],  2 * 16 * 4, 0, cudaMemcpyDeviceToDevice);
    cudaMemcpyToSymbolAsync(cWk,   d_in[9],  2 * 32 * 4, 0, cudaMemcpyDeviceToDevice);
    cudaMemcpyToSymbolAsync(cWv,   d_in[10], 2 * 32 * 4, 0, cudaMemcpyDeviceToDevice);
    cudaMemcpyToSymbolAsync(cWo,   d_in[11], 2 * 16 * 4, 0, cudaMemcpyDeviceToDevice);
    cudaMemcpyToSymbolAsync(cbo,   d_in[12], 2 * 4 * 4,  0, cudaMemcpyDeviceToDevice);
    cudaMemcpyToSymbolAsync(ctw,   d_in[6],  4 * 4,      0, cudaMemcpyDeviceToDevice);
    cudaMemcpyToSymbolAsync(ctb,   d_in[7],  4 * 4,      0, cudaMemcpyDeviceToDevice);
    cudaMemcpyToSymbolAsync(cWlin, d_in[13], 24 * 4,     0, cudaMemcpyDeviceToDevice);
    cudaMemcpyToSymbolAsync(cblin, d_in[14], 2 * 4,      0, cudaMemcpyDeviceToDevice);

    constexpr int NODE_THREADS = 256;
    constexpr int NODE_BLOCKS  = (B * N) / NODE_THREADS;   // 1024
    constexpr int EDGE_BLOCKS  = B * BPB;                  // 1024

    init_kernel<<<NODE_BLOCKS, NODE_THREADS>>>();

    edge_pass<0><<<EDGE_BLOCKS, EDGE_THREADS, EDGE_SMEM>>>(
        x, edge_index, edge_time, timestamp);
    edge_pass<1><<<EDGE_BLOCKS, EDGE_THREADS, EDGE_SMEM>>>(
        x, edge_index, edge_time, timestamp);

    final_kernel<<<1, 256>>>(x, src_index, dst_index, timestamp, out);
}

// round 8
// speedup vs baseline: 1.0917x; 1.0917x over previous
#include <cuda_runtime.h>
#include <math.h>

namespace {

constexpr int B = 128;
constexpr int N = 2048;
constexpr int E = 32768;
constexpr float INV_SQRT_DH = 0.7071067811865476f;

// Node state (h1 after layer0, h2 after layer1), 4 MB
__device__ float g_h[B * N * 4];
// Interleaved accumulators: per node 8 floats = [agg0..3 | s0 s1 | pad pad].
__device__ float g_acc0[B * N * 8];   // 8 MB
__device__ float g_acc1[B * N * 8];   // 8 MB

// Weights in constant memory (filled by capturable D2D copies each launch)
__constant__ float cWq[2 * 16];
__constant__ float cWk[2 * 32];
__constant__ float cWv[2 * 32];
__constant__ float cWo[2 * 16];
__constant__ float cbo[2 * 4];
__constant__ float ctw[4];
__constant__ float ctb[4];
__constant__ float cWlin[24];
__constant__ float cblin[2];

// Node update for layer L: h_next = relu(h + (agg/s) @ Wo[L] + bo[L])
__device__ __forceinline__ float4 node_update(int L, float4 h,
                                              float4 agg, float4 sv) {
    float s0 = (sv.x == 0.0f) ? 1.0f : sv.x;
    float s1 = (sv.y == 0.0f) ? 1.0f : sv.y;
    float r0 = __frcp_rn(s0);
    float r1 = __frcp_rn(s1);
    float a0 = agg.x * r0, a1 = agg.y * r0;
    float a2 = agg.z * r1, a3 = agg.w * r1;
    const float* Wo = cWo + L * 16;
    const float* bo = cbo + L * 4;
    float hin[4] = {h.x, h.y, h.z, h.w};
    float hn[4];
#pragma unroll
    for (int j = 0; j < 4; j++) {
        float v = hin[j] + bo[j];
        v = fmaf(a0, Wo[0 * 4 + j], v);
        v = fmaf(a1, Wo[1 * 4 + j], v);
        v = fmaf(a2, Wo[2 * 4 + j], v);
        v = fmaf(a3, Wo[3 * 4 + j], v);
        hn[j] = fmaxf(v, 0.0f);
    }
    return make_float4(hn[0], hn[1], hn[2], hn[3]);
}

// ---------------------------------------------------------------------------
// Init: zero both accumulator buffers.
// ---------------------------------------------------------------------------
__global__ void __launch_bounds__(256) init_kernel() {
    int idx = blockIdx.x * blockDim.x + threadIdx.x;   // 0 .. B*N-1
    float4 z = make_float4(0.f, 0.f, 0.f, 0.f);
    reinterpret_cast<float4*>(g_acc0)[idx * 2 + 0] = z;
    reinterpret_cast<float4*>(g_acc0)[idx * 2 + 1] = z;
    reinterpret_cast<float4*>(g_acc1)[idx * 2 + 0] = z;
    reinterpret_cast<float4*>(g_acc1)[idx * 2 + 1] = z;
}

// ---------------------------------------------------------------------------
// Edge pass: stage the batch h tile (32 KB) in smem; two edges per thread per
// iteration with vector edge loads; 2 vector REDs per edge into acc.
// ---------------------------------------------------------------------------
constexpr int BPB = 16;                        // blocks per batch
constexpr int EDGE_THREADS = 256;
constexpr int EDGES_PER_BLOCK = E / BPB;       // 2048
constexpr int PAIR_ITERS = EDGES_PER_BLOCK / (EDGE_THREADS * 2);  // 4
constexpr int EDGE_SMEM = N * 16;              // 32 KB (h tile)

template <int L>
__device__ __forceinline__ void process_edge(
        const float4* __restrict__ sh, float* __restrict__ acc_base,
        int src, int dst, float dt) {
    const float* Wk = cWk + L * 32;
    const float* Wv = cWv + L * 32;
    const float* Wq = cWq + L * 16;

    float4 hs = sh[src];
    float msg[8];
    msg[0] = hs.x; msg[1] = hs.y; msg[2] = hs.z; msg[3] = hs.w;
#pragma unroll
    for (int j = 0; j < 4; j++) msg[4 + j] = __cosf(fmaf(dt, ctw[j], ctb[j]));

    float k[4];
#pragma unroll
    for (int j = 0; j < 4; j++) {
        float acc = msg[0] * Wk[0 * 4 + j];
#pragma unroll
        for (int i = 1; i < 8; i++) acc = fmaf(msg[i], Wk[i * 4 + j], acc);
        k[j] = acc;
    }

    float4 hd = sh[dst];
    float q[4];
#pragma unroll
    for (int j = 0; j < 4; j++) {
        float acc = hd.x * Wq[0 * 4 + j];
        acc = fmaf(hd.y, Wq[1 * 4 + j], acc);
        acc = fmaf(hd.z, Wq[2 * 4 + j], acc);
        acc = fmaf(hd.w, Wq[3 * 4 + j], acc);
        q[j] = acc;
    }

    float l0 = (q[0] * k[0] + q[1] * k[1]) * INV_SQRT_DH;
    float l1 = (q[2] * k[2] + q[3] * k[3]) * INV_SQRT_DH;
    float p0 = __expf(fminf(l0, 80.0f));
    float p1 = __expf(fminf(l1, 80.0f));

    float v[4];
#pragma unroll
    for (int j = 0; j < 4; j++) {
        float acc = msg[0] * Wv[0 * 4 + j];
#pragma unroll
        for (int i = 1; i < 8; i++) acc = fmaf(msg[i], Wv[i * 4 + j], acc);
        v[j] = acc;
    }

    float* nodeacc = acc_base + dst * 8;
    atomicAdd(reinterpret_cast<float4*>(nodeacc),
              make_float4(p0 * v[0], p0 * v[1], p1 * v[2], p1 * v[3]));
    atomicAdd(reinterpret_cast<float2*>(nodeacc + 4),
              make_float2(p0, p1));
}

template <int L>
__global__ void __launch_bounds__(EDGE_THREADS, 5) edge_pass(
        const float* __restrict__ x,
        const int*   __restrict__ edge_index,
        const float* __restrict__ edge_time,
        const float* __restrict__ timestamp) {
    extern __shared__ float4 sh[];   // h tile, N float4

    int b     = blockIdx.x / BPB;
    int chunk = blockIdx.x % BPB;

    // Stage this batch's node states (x for layer 0, g_h for layer 1).
    const float4* hsrc = (L == 0 ? reinterpret_cast<const float4*>(x)
                                 : reinterpret_cast<const float4*>(g_h)) + b * N;
#pragma unroll
    for (int i = threadIdx.x; i < N; i += EDGE_THREADS) sh[i] = hsrc[i];
    __syncthreads();

    int base = chunk * EDGES_PER_BLOCK;
    const int*   e_src = edge_index + (size_t)b * 2 * E + base;
    const int*   e_dst = e_src + E;
    const float* e_t   = edge_time + (size_t)b * E + base;
    float ts = __ldg(timestamp + b);

    float* acc_base = (L == 0 ? g_acc0 : g_acc1) + (size_t)b * N * 8;

    int e = threadIdx.x * 2;
#pragma unroll
    for (int it = 0; it < PAIR_ITERS; it++) {
        int2   s2 = __ldg(reinterpret_cast<const int2*>(e_src + e));
        int2   d2 = __ldg(reinterpret_cast<const int2*>(e_dst + e));
        float2 t2 = __ldg(reinterpret_cast<const float2*>(e_t + e));

        process_edge<L>(sh, acc_base, s2.x, d2.x, ts - t2.x);
        process_edge<L>(sh, acc_base, s2.y, d2.y, ts - t2.y);

        e += EDGE_THREADS * 2;
    }
}

// ---------------------------------------------------------------------------
// Node update kernels.
// ---------------------------------------------------------------------------
__global__ void __launch_bounds__(256) node_kernel0(const float* __restrict__ x) {
    int idx = blockIdx.x * blockDim.x + threadIdx.x;   // 0 .. B*N-1
    float4 h0  = reinterpret_cast<const float4*>(x)[idx];
    float4 agg = reinterpret_cast<const float4*>(g_acc0)[idx * 2 + 0];
    float4 sv  = reinterpret_cast<const float4*>(g_acc0)[idx * 2 + 1];
    reinterpret_cast<float4*>(g_h)[idx] = node_update(0, h0, agg, sv);
}

__global__ void __launch_bounds__(256) node_kernel1() {
    int idx = blockIdx.x * blockDim.x + threadIdx.x;
    float4 h1  = reinterpret_cast<const float4*>(g_h)[idx];
    float4 agg = reinterpret_cast<const float4*>(g_acc1)[idx * 2 + 0];
    float4 sv  = reinterpret_cast<const float4*>(g_acc1)[idx * 2 + 1];
    reinterpret_cast<float4*>(g_h)[idx] = node_update(1, h1, agg, sv);
}

// ---------------------------------------------------------------------------
// Final head: feats = [h[src_idx], h[dst_idx], cos(ts*w+b)] @ W_lin + b_lin
// ---------------------------------------------------------------------------
__global__ void final_kernel(const int*   __restrict__ src_index,
                             const int*   __restrict__ dst_index,
                             const float* __restrict__ timestamp,
                             float* __restrict__ out) {
    int b = threadIdx.x;
    if (b >= B) return;

    float4 hs = reinterpret_cast<const float4*>(g_h)[b * N + src_index[b]];
    float4 hd = reinterpret_cast<const float4*>(g_h)[b * N + dst_index[b]];
    float ts = timestamp[b];

    float f[12];
    f[0] = hs.x; f[1] = hs.y; f[2] = hs.z; f[3] = hs.w;
    f[4] = hd.x; f[5] = hd.y; f[6] = hd.z; f[7] = hd.w;
#pragma unroll
    for (int j = 0; j < 4; j++) f[8 + j] = cosf(fmaf(ts, ctw[j], ctb[j]));

#pragma unroll
    for (int k = 0; k < 2; k++) {
        float acc = cblin[k];
#pragma unroll
        for (int i = 0; i < 12; i++) acc = fmaf(f[i], cWlin[i * 2 + k], acc);
        out[b * 2 + k] = acc;
    }
}

} // anonymous namespace

extern "C" void kernel_launch(void* const* d_in, const int* in_sizes, int n_in,
                              void* d_out, int out_size) {
    const float* x          = (const float*)d_in[0];
    const int*   edge_index = (const int*)  d_in[1];
    const float* edge_time  = (const float*)d_in[2];
    const float* timestamp  = (const float*)d_in[3];
    const int*   src_index  = (const int*)  d_in[4];
    const int*   dst_index  = (const int*)  d_in[5];
    float* out = (float*)d_out;

    // Stage all weights into constant memory (device-to-device, capturable).
    cudaMemcpyToSymbolAsync(cWq,   d_in[8],  2 * 16 * 4, 0, cudaMemcpyDeviceToDevice);
    cudaMemcpyToSymbolAsync(cWk,   d_in[9],  2 * 32 * 4, 0, cudaMemcpyDeviceToDevice);
    cudaMemcpyToSymbolAsync(cWv,   d_in[10], 2 * 32 * 4, 0, cudaMemcpyDeviceToDevice);
    cudaMemcpyToSymbolAsync(cWo,   d_in[11], 2 * 16 * 4, 0, cudaMemcpyDeviceToDevice);
    cudaMemcpyToSymbolAsync(cbo,   d_in[12], 2 * 4 * 4,  0, cudaMemcpyDeviceToDevice);
    cudaMemcpyToSymbolAsync(ctw,   d_in[6],  4 * 4,      0, cudaMemcpyDeviceToDevice);
    cudaMemcpyToSymbolAsync(ctb,   d_in[7],  4 * 4,      0, cudaMemcpyDeviceToDevice);
    cudaMemcpyToSymbolAsync(cWlin, d_in[13], 24 * 4,     0, cudaMemcpyDeviceToDevice);
    cudaMemcpyToSymbolAsync(cblin, d_in[14], 2 * 4,      0, cudaMemcpyDeviceToDevice);

    constexpr int NODE_THREADS = 256;
    constexpr int NODE_BLOCKS  = (B * N) / NODE_THREADS;   // 1024
    constexpr int EDGE_BLOCKS  = B * BPB;                  // 2048

    init_kernel<<<NODE_BLOCKS, NODE_THREADS>>>();

    edge_pass<0><<<EDGE_BLOCKS, EDGE_THREADS, EDGE_SMEM>>>(
        x, edge_index, edge_time, timestamp);
    node_kernel0<<<NODE_BLOCKS, NODE_THREADS>>>(x);

    edge_pass<1><<<EDGE_BLOCKS, EDGE_THREADS, EDGE_SMEM>>>(
        x, edge_index, edge_time, timestamp);
    node_kernel1<<<NODE_BLOCKS, NODE_THREADS>>>();

    final_kernel<<<1, 128>>>(src_index, dst_index, timestamp, out);
}